// round 1
// baseline (speedup 1.0000x reference)
#include <cuda_runtime.h>

#define N_NODES 50000
#define N_EDGES 800000
#define F_IN    128
#define H_DIM   100
#define C_DIM   16
#define LEAKY   0.01f

// ---- scratch (device globals; no allocation allowed) ----
__device__ __align__(16) float g_h1  [N_NODES * H_DIM];   // X @ W1, later leaky(conv1)
__device__ __align__(16) float g_acc1[N_NODES * H_DIM];   // scatter accumulator layer 1
__device__ __align__(16) float g_h2  [N_NODES * C_DIM];   // h1p @ W2
__device__ __align__(16) float g_acc2[N_NODES * C_DIM];   // scatter accumulator layer 2
__device__ float g_dinv[N_NODES];
__device__ int   g_deg [N_NODES];

// ---------------------------------------------------------------- init
__global__ void k_init() {
    int t = blockIdx.x * blockDim.x + threadIdx.x;
    int stride = gridDim.x * blockDim.x;
    for (int i = t; i < N_NODES * H_DIM; i += stride) g_acc1[i] = 0.f;
    for (int i = t; i < N_NODES * C_DIM; i += stride) g_acc2[i] = 0.f;
    for (int i = t; i < N_NODES;         i += stride) g_deg[i]  = 1;   // self-loop
}

// ---------------------------------------------------------------- degree
__global__ void k_deg(const int* __restrict__ dst) {
    int e = blockIdx.x * blockDim.x + threadIdx.x;
    if (e < N_EDGES) atomicAdd(&g_deg[dst[e]], 1);
}

__global__ void k_dinv() {
    int i = blockIdx.x * blockDim.x + threadIdx.x;
    if (i < N_NODES) g_dinv[i] = rsqrtf((float)g_deg[i]);
}

// ---------------------------------------------------------------- GEMM1: g_h1 = x @ W1   (N x 128 @ 128 x 100)
// BM=64 rows, BN=128 (H padded), BK=16. Thread tile 4x8, 256 threads.
__global__ void k_gemm1(const float* __restrict__ x, const float* __restrict__ W1) {
    __shared__ __align__(16) float sx[64][17];    // padded: column reads
    __shared__ __align__(16) float sw[16][128];

    int tid  = threadIdx.x;
    int tcol = tid & 15;     // 0..15 -> 8 cols each
    int trow = tid >> 4;     // 0..15 -> 4 rows each
    int r0   = blockIdx.x * 64;

    float acc[4][8];
    #pragma unroll
    for (int i = 0; i < 4; i++)
        #pragma unroll
        for (int j = 0; j < 8; j++) acc[i][j] = 0.f;

    for (int k0 = 0; k0 < F_IN; k0 += 16) {
        // load x tile 64x16
        #pragma unroll
        for (int i = tid; i < 64 * 16; i += 256) {
            int r = i >> 4, c = i & 15;
            int gr = r0 + r;
            sx[r][c] = (gr < N_NODES) ? x[gr * F_IN + k0 + c] : 0.f;
        }
        // load W1 tile 16x128 (cols >= 100 zero)
        #pragma unroll
        for (int i = tid; i < 16 * 128; i += 256) {
            int r = i >> 7, c = i & 127;
            sw[r][c] = (c < H_DIM) ? W1[(k0 + r) * H_DIM + c] : 0.f;
        }
        __syncthreads();

        #pragma unroll
        for (int k = 0; k < 16; k++) {
            float xv[4];
            #pragma unroll
            for (int i = 0; i < 4; i++) xv[i] = sx[trow * 4 + i][k];
            float4 wa = *(const float4*)&sw[k][tcol * 8];
            float4 wb = *(const float4*)&sw[k][tcol * 8 + 4];
            #pragma unroll
            for (int i = 0; i < 4; i++) {
                acc[i][0] += xv[i] * wa.x;  acc[i][1] += xv[i] * wa.y;
                acc[i][2] += xv[i] * wa.z;  acc[i][3] += xv[i] * wa.w;
                acc[i][4] += xv[i] * wb.x;  acc[i][5] += xv[i] * wb.y;
                acc[i][6] += xv[i] * wb.z;  acc[i][7] += xv[i] * wb.w;
            }
        }
        __syncthreads();
    }

    #pragma unroll
    for (int i = 0; i < 4; i++) {
        int gr = r0 + trow * 4 + i;
        if (gr < N_NODES) {
            #pragma unroll
            for (int j = 0; j < 8; j++) {
                int gc = tcol * 8 + j;
                if (gc < H_DIM) g_h1[gr * H_DIM + gc] = acc[i][j];
            }
        }
    }
}

// ---------------------------------------------------------------- prop1: warp per edge, 25 lanes x float4
__global__ void k_prop1(const int* __restrict__ src, const int* __restrict__ dst) {
    int gw   = (blockIdx.x * blockDim.x + threadIdx.x) >> 5;
    int lane = threadIdx.x & 31;
    if (gw >= N_EDGES) return;
    int s = src[gw];
    int d = dst[gw];
    float norm = g_dinv[s] * g_dinv[d];
    if (lane < 25) {
        float4 v = ((const float4*)(g_h1 + s * H_DIM))[lane];
        float* out = g_acc1 + d * H_DIM + lane * 4;
        atomicAdd(out + 0, v.x * norm);
        atomicAdd(out + 1, v.y * norm);
        atomicAdd(out + 2, v.z * norm);
        atomicAdd(out + 3, v.w * norm);
    }
}

// ---------------------------------------------------------------- epilogue 1: self-loop + bias + leaky, in place into g_h1
__global__ void k_epi1(const float* __restrict__ b1) {
    int t = blockIdx.x * blockDim.x + threadIdx.x;
    if (t >= N_NODES * H_DIM) return;
    int i = t / H_DIM;
    int j = t - i * H_DIM;
    float di = g_dinv[i];
    float v = g_acc1[t] + g_h1[t] * di * di + b1[j];
    g_h1[t] = (v > 0.f) ? v : LEAKY * v;
}

// ---------------------------------------------------------------- GEMM2: g_h2 = h1p @ W2  (N x 100 @ 100 x 16)
// 128 threads, 64 rows/block; thread = 2 rows x 4 cols
__global__ void k_gemm2(const float* __restrict__ W2) {
    __shared__ __align__(16) float sh[64][101];            // pitch 101: conflict-free column reads
    __shared__ __align__(16) float sw[H_DIM * C_DIM];

    int tid = threadIdx.x;
    int r0  = blockIdx.x * 64;

    for (int i = tid; i < H_DIM * C_DIM; i += 128) sw[i] = W2[i];
    for (int i = tid; i < 64 * H_DIM; i += 128) {
        int r = i / H_DIM, c = i - r * H_DIM;
        int gr = r0 + r;
        sh[r][c] = (gr < N_NODES) ? g_h1[gr * H_DIM + c] : 0.f;
    }
    __syncthreads();

    int cg = tid & 3;       // 4 cols per thread
    int rg = tid >> 2;      // 0..31 -> rows rg*2, rg*2+1
    float a0x=0,a0y=0,a0z=0,a0w=0, a1x=0,a1y=0,a1z=0,a1w=0;

    #pragma unroll 4
    for (int k = 0; k < H_DIM; k++) {
        float x0 = sh[rg * 2 + 0][k];
        float x1 = sh[rg * 2 + 1][k];
        float4 w = *(const float4*)&sw[k * C_DIM + cg * 4];
        a0x += x0 * w.x;  a0y += x0 * w.y;  a0z += x0 * w.z;  a0w += x0 * w.w;
        a1x += x1 * w.x;  a1y += x1 * w.y;  a1z += x1 * w.z;  a1w += x1 * w.w;
    }

    int gr0 = r0 + rg * 2;
    if (gr0 < N_NODES)
        *(float4*)&g_h2[gr0 * C_DIM + cg * 4] = make_float4(a0x, a0y, a0z, a0w);
    if (gr0 + 1 < N_NODES)
        *(float4*)&g_h2[(gr0 + 1) * C_DIM + cg * 4] = make_float4(a1x, a1y, a1z, a1w);
}

// ---------------------------------------------------------------- prop2: 16 lanes per edge
__global__ void k_prop2(const int* __restrict__ src, const int* __restrict__ dst) {
    int t = blockIdx.x * blockDim.x + threadIdx.x;
    int e = t >> 4;
    int j = t & 15;
    if (e >= N_EDGES) return;
    int s = src[e];
    int d = dst[e];
    float norm = g_dinv[s] * g_dinv[d];
    atomicAdd(&g_acc2[d * C_DIM + j], g_h2[s * C_DIM + j] * norm);
}

// ---------------------------------------------------------------- final: self-loop + bias + log_softmax over 16
__global__ void k_final(const float* __restrict__ b2, float* __restrict__ out) {
    int t = blockIdx.x * blockDim.x + threadIdx.x;
    int i = t >> 4;
    int j = t & 15;
    if (i >= N_NODES) return;
    float di = g_dinv[i];
    float v = g_acc2[t] + g_h2[t] * di * di + b2[j];

    // reductions within the 16-lane group (xor masks < 16 stay in-group)
    float m = v;
    #pragma unroll
    for (int s = 8; s >= 1; s >>= 1) m = fmaxf(m, __shfl_xor_sync(0xFFFFFFFFu, m, s));
    float ex = expf(v - m);
    float ssum = ex;
    #pragma unroll
    for (int s = 8; s >= 1; s >>= 1) ssum += __shfl_xor_sync(0xFFFFFFFFu, ssum, s);
    out[t] = v - m - logf(ssum);
}

// ---------------------------------------------------------------- launch
extern "C" void kernel_launch(void* const* d_in, const int* in_sizes, int n_in,
                              void* d_out, int out_size) {
    const float* x  = (const float*)d_in[0];
    const float* W1 = (const float*)d_in[1];
    const float* b1 = (const float*)d_in[2];
    const float* W2 = (const float*)d_in[3];
    const float* b2 = (const float*)d_in[4];
    const int*   ei = (const int*)d_in[5];
    const int* src = ei;
    const int* dst = ei + N_EDGES;
    float* out = (float*)d_out;

    k_init <<< (N_NODES * H_DIM + 255) / 256, 256 >>> ();
    k_deg  <<< (N_EDGES + 255) / 256, 256 >>> (dst);
    k_dinv <<< (N_NODES + 255) / 256, 256 >>> ();
    k_gemm1<<< (N_NODES + 63) / 64, 256 >>> (x, W1);
    k_prop1<<< (N_EDGES * 32 + 255) / 256, 256 >>> (src, dst);
    k_epi1 <<< (N_NODES * H_DIM + 255) / 256, 256 >>> (b1);
    k_gemm2<<< (N_NODES + 63) / 64, 128 >>> (W2);
    k_prop2<<< (N_EDGES * 16 + 255) / 256, 256 >>> (src, dst);
    k_final<<< (N_NODES * 16 + 255) / 256, 256 >>> (b2, out);
}

// round 2
// speedup vs baseline: 1.7909x; 1.7909x over previous
#include <cuda_runtime.h>

#define N_NODES 50000
#define N_EDGES 800000
#define F_IN    128
#define H_DIM   100
#define C_DIM   16
#define LEAKY   0.01f

// ---- scratch (device globals; no allocation allowed) ----
__device__ __align__(16) float g_h1 [N_NODES * H_DIM];   // X @ W1
__device__ __align__(16) float g_h1p[N_NODES * H_DIM];   // leaky(conv1 out)
__device__ __align__(16) float g_h2 [N_NODES * C_DIM];   // h1p @ W2
__device__ float g_dinv[N_NODES];
__device__ int   g_cnt [N_NODES];
__device__ int   g_rowptr[N_NODES + 1];
__device__ int   g_cursor[N_NODES];
__device__ int   g_col[N_EDGES];
__device__ float g_val[N_EDGES];

// ---------------------------------------------------------------- zero counts
__global__ void k_zero() {
    int i = blockIdx.x * blockDim.x + threadIdx.x;
    if (i < N_NODES) g_cnt[i] = 0;
}

// ---------------------------------------------------------------- in-degree count (real edges only)
__global__ void k_count(const int* __restrict__ dst) {
    int e = blockIdx.x * blockDim.x + threadIdx.x;
    if (e < N_EDGES) atomicAdd(&g_cnt[dst[e]], 1);
}

// ---------------------------------------------------------------- single-block scan: row_ptr, cursor, dinv
__global__ void k_scan() {
    __shared__ int wsum[32];
    __shared__ int chunk_total;
    int tid = threadIdx.x, lane = tid & 31, wid = tid >> 5;
    int run = 0;
    for (int base = 0; base < N_NODES; base += 1024) {
        int i = base + tid;
        int v = (i < N_NODES) ? g_cnt[i] : 0;
        // warp inclusive scan
        int incl = v;
        #pragma unroll
        for (int off = 1; off < 32; off <<= 1) {
            int t = __shfl_up_sync(0xFFFFFFFFu, incl, off);
            if (lane >= off) incl += t;
        }
        if (lane == 31) wsum[wid] = incl;
        __syncthreads();
        if (wid == 0) {
            int wv = wsum[lane];
            int winc = wv;
            #pragma unroll
            for (int off = 1; off < 32; off <<= 1) {
                int t = __shfl_up_sync(0xFFFFFFFFu, winc, off);
                if (lane >= off) winc += t;
            }
            wsum[lane] = winc - wv;      // exclusive warp offsets
            if (lane == 31) chunk_total = winc;
        }
        __syncthreads();
        int excl = run + wsum[wid] + incl - v;
        if (i < N_NODES) {
            g_rowptr[i] = excl;
            g_cursor[i] = excl;
            g_dinv[i] = rsqrtf((float)(v + 1));   // +1 self-loop
        }
        run += chunk_total;
        __syncthreads();
    }
    if (tid == 0) g_rowptr[N_NODES] = run;
}

// ---------------------------------------------------------------- scatter edges into CSR (by dst), precompute norm
__global__ void k_build(const int* __restrict__ src, const int* __restrict__ dst) {
    int e = blockIdx.x * blockDim.x + threadIdx.x;
    if (e >= N_EDGES) return;
    int s = src[e], d = dst[e];
    int p = atomicAdd(&g_cursor[d], 1);
    g_col[p] = s;
    g_val[p] = g_dinv[s] * g_dinv[d];
}

// ---------------------------------------------------------------- GEMM1: g_h1 = x @ W1   (N x 128 @ 128 x 100)
// BM=128, BN=128(pad), BK=8, 256 threads, 8x8 thread tile.
__global__ void k_gemm1(const float* __restrict__ x, const float* __restrict__ W1) {
    __shared__ __align__(16) float sxT[8][128];   // k-major x tile
    __shared__ __align__(16) float sw [8][128];

    int tid  = threadIdx.x;
    int tcol = tid & 15;      // 0..15 -> cols tcol*8..+7
    int trow = tid >> 4;      // 0..15 -> rows trow*8..+7
    int r0   = blockIdx.x * 128;

    float acc[8][8];
    #pragma unroll
    for (int i = 0; i < 8; i++)
        #pragma unroll
        for (int j = 0; j < 8; j++) acc[i][j] = 0.f;

    int xrow  = tid >> 1;
    int xhalf = tid & 1;
    int wrow  = tid >> 5;           // 0..7
    int wcol  = (tid & 31) * 4;     // 0..124

    for (int k0 = 0; k0 < F_IN; k0 += 8) {
        // x tile 128x8 -> k-major smem
        float4 xv = make_float4(0.f, 0.f, 0.f, 0.f);
        int gr = r0 + xrow;
        if (gr < N_NODES) xv = *(const float4*)&x[gr * F_IN + k0 + xhalf * 4];
        sxT[xhalf * 4 + 0][xrow] = xv.x;
        sxT[xhalf * 4 + 1][xrow] = xv.y;
        sxT[xhalf * 4 + 2][xrow] = xv.z;
        sxT[xhalf * 4 + 3][xrow] = xv.w;
        // w tile 8x128 (cols >= 100 zero)
        float4 wv = make_float4(0.f, 0.f, 0.f, 0.f);
        if (wcol < H_DIM) wv = *(const float4*)&W1[(k0 + wrow) * H_DIM + wcol];
        *(float4*)&sw[wrow][wcol] = wv;
        __syncthreads();

        #pragma unroll
        for (int k = 0; k < 8; k++) {
            float4 a0 = *(const float4*)&sxT[k][trow * 8];
            float4 a1 = *(const float4*)&sxT[k][trow * 8 + 4];
            float4 b0 = *(const float4*)&sw[k][tcol * 8];
            float4 b1 = *(const float4*)&sw[k][tcol * 8 + 4];
            float av[8] = {a0.x, a0.y, a0.z, a0.w, a1.x, a1.y, a1.z, a1.w};
            float bv[8] = {b0.x, b0.y, b0.z, b0.w, b1.x, b1.y, b1.z, b1.w};
            #pragma unroll
            for (int i = 0; i < 8; i++)
                #pragma unroll
                for (int j = 0; j < 8; j++)
                    acc[i][j] += av[i] * bv[j];
        }
        __syncthreads();
    }

    #pragma unroll
    for (int i = 0; i < 8; i++) {
        int gr = r0 + trow * 8 + i;
        if (gr >= N_NODES) continue;
        #pragma unroll
        for (int jj = 0; jj < 8; jj += 4) {
            int gc = tcol * 8 + jj;
            if (gc < H_DIM)   // H_DIM % 4 == 0, so full float4 always fits
                *(float4*)&g_h1[gr * H_DIM + gc] =
                    make_float4(acc[i][jj], acc[i][jj+1], acc[i][jj+2], acc[i][jj+3]);
        }
    }
}

// ---------------------------------------------------------------- prop1 fused: gather-reduce + self-loop + bias + leaky
// warp per node; lanes 0..24 each own a float4 (100 feats).
__global__ void k_prop1f(const float* __restrict__ b1) {
    int gw   = (blockIdx.x * blockDim.x + threadIdx.x) >> 5;
    int lane = threadIdx.x & 31;
    if (gw >= N_NODES) return;
    int beg = g_rowptr[gw];
    int end = g_rowptr[gw + 1];
    bool act = lane < 25;
    int off = lane * 4;

    float4 acc = make_float4(0.f, 0.f, 0.f, 0.f);
    int j = beg;
    for (; j + 1 < end; j += 2) {
        int   s0 = g_col[j],  s1 = g_col[j + 1];
        float w0 = g_val[j],  w1 = g_val[j + 1];
        if (act) {
            float4 v0 = *(const float4*)(g_h1 + s0 * H_DIM + off);
            float4 v1 = *(const float4*)(g_h1 + s1 * H_DIM + off);
            acc.x += w0 * v0.x + w1 * v1.x;
            acc.y += w0 * v0.y + w1 * v1.y;
            acc.z += w0 * v0.z + w1 * v1.z;
            acc.w += w0 * v0.w + w1 * v1.w;
        }
    }
    if (j < end) {
        int s = g_col[j]; float w = g_val[j];
        if (act) {
            float4 v = *(const float4*)(g_h1 + s * H_DIM + off);
            acc.x += w * v.x; acc.y += w * v.y; acc.z += w * v.z; acc.w += w * v.w;
        }
    }
    if (act) {
        float di = g_dinv[gw];
        float sl = di * di;
        float4 own = *(const float4*)(g_h1 + gw * H_DIM + off);
        float4 bb  = *(const float4*)(b1 + off);
        float4 r;
        r.x = acc.x + sl * own.x + bb.x;
        r.y = acc.y + sl * own.y + bb.y;
        r.z = acc.z + sl * own.z + bb.z;
        r.w = acc.w + sl * own.w + bb.w;
        r.x = (r.x > 0.f) ? r.x : LEAKY * r.x;
        r.y = (r.y > 0.f) ? r.y : LEAKY * r.y;
        r.z = (r.z > 0.f) ? r.z : LEAKY * r.z;
        r.w = (r.w > 0.f) ? r.w : LEAKY * r.w;
        *(float4*)(g_h1p + gw * H_DIM + off) = r;
    }
}

// ---------------------------------------------------------------- GEMM2: g_h2 = h1p @ W2  (N x 100 @ 100 x 16)
__global__ void k_gemm2(const float* __restrict__ W2) {
    __shared__ __align__(16) float sh[64][101];
    __shared__ __align__(16) float sw[H_DIM * C_DIM];

    int tid = threadIdx.x;
    int r0  = blockIdx.x * 64;

    for (int i = tid; i < H_DIM * C_DIM; i += 128) sw[i] = W2[i];
    for (int i = tid; i < 64 * H_DIM; i += 128) {
        int r = i / H_DIM, c = i - r * H_DIM;
        int gr = r0 + r;
        sh[r][c] = (gr < N_NODES) ? g_h1p[gr * H_DIM + c] : 0.f;
    }
    __syncthreads();

    int cg = tid & 3;
    int rg = tid >> 2;
    float a0x=0,a0y=0,a0z=0,a0w=0, a1x=0,a1y=0,a1z=0,a1w=0;

    #pragma unroll 4
    for (int k = 0; k < H_DIM; k++) {
        float x0 = sh[rg * 2 + 0][k];
        float x1 = sh[rg * 2 + 1][k];
        float4 w = *(const float4*)&sw[k * C_DIM + cg * 4];
        a0x += x0 * w.x;  a0y += x0 * w.y;  a0z += x0 * w.z;  a0w += x0 * w.w;
        a1x += x1 * w.x;  a1y += x1 * w.y;  a1z += x1 * w.z;  a1w += x1 * w.w;
    }

    int gr0 = r0 + rg * 2;
    if (gr0 < N_NODES)
        *(float4*)&g_h2[gr0 * C_DIM + cg * 4] = make_float4(a0x, a0y, a0z, a0w);
    if (gr0 + 1 < N_NODES)
        *(float4*)&g_h2[(gr0 + 1) * C_DIM + cg * 4] = make_float4(a1x, a1y, a1z, a1w);
}

// ---------------------------------------------------------------- prop2 fused: gather-reduce + self-loop + bias + log_softmax
// warp per node; two edges per iteration (half-warp each), 16 feats per edge.
__global__ void k_prop2f(const float* __restrict__ b2, float* __restrict__ out) {
    int gw   = (blockIdx.x * blockDim.x + threadIdx.x) >> 5;
    int lane = threadIdx.x & 31;
    if (gw >= N_NODES) return;
    int beg = g_rowptr[gw];
    int end = g_rowptr[gw + 1];
    int sub = lane >> 4;       // edge slot 0/1
    int f   = lane & 15;

    float acc = 0.f;
    for (int j = beg + sub; j < end; j += 2) {
        int s = g_col[j];
        float w = g_val[j];
        acc += w * g_h2[s * C_DIM + f];
    }
    acc += __shfl_xor_sync(0xFFFFFFFFu, acc, 16);

    float di = g_dinv[gw];
    float v = acc + di * di * g_h2[gw * C_DIM + f] + b2[f];

    float m = v;
    #pragma unroll
    for (int s = 8; s >= 1; s >>= 1) m = fmaxf(m, __shfl_xor_sync(0xFFFFFFFFu, m, s));
    float ex = expf(v - m);
    float ssum = ex;
    #pragma unroll
    for (int s = 8; s >= 1; s >>= 1) ssum += __shfl_xor_sync(0xFFFFFFFFu, ssum, s);
    if (lane < 16) out[gw * C_DIM + f] = v - m - logf(ssum);
}

// ---------------------------------------------------------------- launch
extern "C" void kernel_launch(void* const* d_in, const int* in_sizes, int n_in,
                              void* d_out, int out_size) {
    const float* x  = (const float*)d_in[0];
    const float* W1 = (const float*)d_in[1];
    const float* b1 = (const float*)d_in[2];
    const float* W2 = (const float*)d_in[3];
    const float* b2 = (const float*)d_in[4];
    const int*   ei = (const int*)d_in[5];
    const int* src = ei;
    const int* dst = ei + N_EDGES;
    float* out = (float*)d_out;

    k_zero  <<< (N_NODES + 255) / 256, 256 >>> ();
    k_count <<< (N_EDGES + 255) / 256, 256 >>> (dst);
    k_scan  <<< 1, 1024 >>> ();
    k_build <<< (N_EDGES + 255) / 256, 256 >>> (src, dst);
    k_gemm1 <<< (N_NODES + 127) / 128, 256 >>> (x, W1);
    k_prop1f<<< (N_NODES * 32 + 255) / 256, 256 >>> (b1);
    k_gemm2 <<< (N_NODES + 63) / 64, 128 >>> (W2);
    k_prop2f<<< (N_NODES * 32 + 255) / 256, 256 >>> (b2, out);
}

// round 3
// speedup vs baseline: 2.5496x; 1.4237x over previous
#include <cuda_runtime.h>

#define N_NODES 50000
#define N_EDGES 800000
#define F_IN    128
#define H_DIM   100
#define C_DIM   16
#define LEAKY   0.01f

#define SCAN_BLK   49            // ceil(50000 / 1024)
#define CNT_PAD    (SCAN_BLK * 1024)   // 50176

// ---- scratch (device globals; no allocation allowed) ----
__device__ __align__(16) float g_h1 [N_NODES * H_DIM];   // X @ W1
__device__ __align__(16) float g_h1p[N_NODES * H_DIM];   // leaky(conv1 out)
__device__ __align__(16) float g_h2 [N_NODES * C_DIM];   // h1p @ W2
__device__ float g_dinv[N_NODES];
__device__ __align__(16) int g_cnt[CNT_PAD];
__device__ int   g_rowptr[N_NODES + 1];
__device__ int   g_cursor[N_NODES];
__device__ int   g_col[N_EDGES];
__device__ float g_val[N_EDGES];
__device__ int   g_bsum[SCAN_BLK];
__device__ int   g_boff[SCAN_BLK];

// ---------------------------------------------------------------- zero counts (incl. padding)
__global__ void k_zero() {
    int i = blockIdx.x * blockDim.x + threadIdx.x;
    if (i < CNT_PAD) g_cnt[i] = 0;
}

// ---------------------------------------------------------------- in-degree count, 4 edges/thread
__global__ void k_count(const int* __restrict__ dst) {
    int t = blockIdx.x * blockDim.x + threadIdx.x;
    if (t < N_EDGES / 4) {
        int4 d = ((const int4*)dst)[t];
        atomicAdd(&g_cnt[d.x], 1);
        atomicAdd(&g_cnt[d.y], 1);
        atomicAdd(&g_cnt[d.z], 1);
        atomicAdd(&g_cnt[d.w], 1);
    }
}

// ---------------------------------------------------------------- scan stage 1: per-block sums (1024 elems/block)
__global__ void k_scan1() {
    __shared__ int wsum[8];
    int b = blockIdx.x, tid = threadIdx.x, lane = tid & 31, wid = tid >> 5;
    int4 c = *(const int4*)&g_cnt[b * 1024 + tid * 4];
    int v = c.x + c.y + c.z + c.w;
    #pragma unroll
    for (int off = 16; off >= 1; off >>= 1) v += __shfl_xor_sync(0xFFFFFFFFu, v, off);
    if (lane == 0) wsum[wid] = v;
    __syncthreads();
    if (tid == 0) {
        int s = 0;
        #pragma unroll
        for (int i = 0; i < 8; i++) s += wsum[i];
        g_bsum[b] = s;
    }
}

// ---------------------------------------------------------------- scan stage 2: exclusive scan of 49 block sums
__global__ void k_scan2() {
    __shared__ int w0tot;
    int tid = threadIdx.x;   // 64 threads
    int v = (tid < SCAN_BLK) ? g_bsum[tid] : 0;
    int incl = v;
    #pragma unroll
    for (int off = 1; off < 32; off <<= 1) {
        int t = __shfl_up_sync(0xFFFFFFFFu, incl, off);
        if ((tid & 31) >= off) incl += t;
    }
    if (tid == 31) w0tot = incl;
    __syncthreads();
    int excl = incl - v + ((tid >= 32) ? w0tot : 0);
    if (tid < SCAN_BLK) g_boff[tid] = excl;
    if (tid == 0) g_rowptr[N_NODES] = N_EDGES;
}

// ---------------------------------------------------------------- scan stage 3: emit rowptr/cursor/dinv
__global__ void k_scan3() {
    __shared__ int wsum[8];
    int b = blockIdx.x, tid = threadIdx.x, lane = tid & 31, wid = tid >> 5;
    int base = b * 1024 + tid * 4;
    int4 c = *(const int4*)&g_cnt[base];
    int tsum = c.x + c.y + c.z + c.w;
    int incl = tsum;
    #pragma unroll
    for (int off = 1; off < 32; off <<= 1) {
        int t = __shfl_up_sync(0xFFFFFFFFu, incl, off);
        if (lane >= off) incl += t;
    }
    if (lane == 31) wsum[wid] = incl;
    __syncthreads();
    if (tid == 0) {
        int r = 0;
        #pragma unroll
        for (int i = 0; i < 8; i++) { int t = wsum[i]; wsum[i] = r; r += t; }
    }
    __syncthreads();
    int e = g_boff[b] + wsum[wid] + incl - tsum;
    int cv[4] = {c.x, c.y, c.z, c.w};
    #pragma unroll
    for (int k = 0; k < 4; k++) {
        int i = base + k;
        if (i < N_NODES) {
            g_rowptr[i] = e;
            g_cursor[i] = e;
            g_dinv[i] = rsqrtf((float)(cv[k] + 1));
        }
        e += cv[k];
    }
}

// ---------------------------------------------------------------- build CSR, 4 edges/thread
__global__ void k_build(const int* __restrict__ src, const int* __restrict__ dst) {
    int t = blockIdx.x * blockDim.x + threadIdx.x;
    if (t >= N_EDGES / 4) return;
    int4 s4 = ((const int4*)src)[t];
    int4 d4 = ((const int4*)dst)[t];
    int sv[4] = {s4.x, s4.y, s4.z, s4.w};
    int dv[4] = {d4.x, d4.y, d4.z, d4.w};
    #pragma unroll
    for (int k = 0; k < 4; k++) {
        int p = atomicAdd(&g_cursor[dv[k]], 1);
        g_col[p] = sv[k];
        g_val[p] = g_dinv[sv[k]] * g_dinv[dv[k]];
    }
}

// ---------------------------------------------------------------- GEMM1: g_h1 = x @ W1   (N x 128 @ 128 x 100)
__global__ void k_gemm1(const float* __restrict__ x, const float* __restrict__ W1) {
    __shared__ __align__(16) float sxT[8][128];
    __shared__ __align__(16) float sw [8][128];

    int tid  = threadIdx.x;
    int tcol = tid & 15;
    int trow = tid >> 4;
    int r0   = blockIdx.x * 128;

    float acc[8][8];
    #pragma unroll
    for (int i = 0; i < 8; i++)
        #pragma unroll
        for (int j = 0; j < 8; j++) acc[i][j] = 0.f;

    int xrow  = tid >> 1;
    int xhalf = tid & 1;
    int wrow  = tid >> 5;
    int wcol  = (tid & 31) * 4;

    for (int k0 = 0; k0 < F_IN; k0 += 8) {
        float4 xv = make_float4(0.f, 0.f, 0.f, 0.f);
        int gr = r0 + xrow;
        if (gr < N_NODES) xv = *(const float4*)&x[gr * F_IN + k0 + xhalf * 4];
        sxT[xhalf * 4 + 0][xrow] = xv.x;
        sxT[xhalf * 4 + 1][xrow] = xv.y;
        sxT[xhalf * 4 + 2][xrow] = xv.z;
        sxT[xhalf * 4 + 3][xrow] = xv.w;
        float4 wv = make_float4(0.f, 0.f, 0.f, 0.f);
        if (wcol < H_DIM) wv = *(const float4*)&W1[(k0 + wrow) * H_DIM + wcol];
        *(float4*)&sw[wrow][wcol] = wv;
        __syncthreads();

        #pragma unroll
        for (int k = 0; k < 8; k++) {
            float4 a0 = *(const float4*)&sxT[k][trow * 8];
            float4 a1 = *(const float4*)&sxT[k][trow * 8 + 4];
            float4 b0 = *(const float4*)&sw[k][tcol * 8];
            float4 b1 = *(const float4*)&sw[k][tcol * 8 + 4];
            float av[8] = {a0.x, a0.y, a0.z, a0.w, a1.x, a1.y, a1.z, a1.w};
            float bv[8] = {b0.x, b0.y, b0.z, b0.w, b1.x, b1.y, b1.z, b1.w};
            #pragma unroll
            for (int i = 0; i < 8; i++)
                #pragma unroll
                for (int j = 0; j < 8; j++)
                    acc[i][j] += av[i] * bv[j];
        }
        __syncthreads();
    }

    #pragma unroll
    for (int i = 0; i < 8; i++) {
        int gr = r0 + trow * 8 + i;
        if (gr >= N_NODES) continue;
        #pragma unroll
        for (int jj = 0; jj < 8; jj += 4) {
            int gc = tcol * 8 + jj;
            if (gc < H_DIM)
                *(float4*)&g_h1[gr * H_DIM + gc] =
                    make_float4(acc[i][jj], acc[i][jj+1], acc[i][jj+2], acc[i][jj+3]);
        }
    }
}

// ---------------------------------------------------------------- prop1 fused: gather + self-loop + bias + leaky (x4 unroll)
__global__ void k_prop1f(const float* __restrict__ b1) {
    int gw   = (blockIdx.x * blockDim.x + threadIdx.x) >> 5;
    int lane = threadIdx.x & 31;
    if (gw >= N_NODES) return;
    int beg = g_rowptr[gw];
    int end = g_rowptr[gw + 1];
    bool act = lane < 25;
    int off = lane * 4;

    float4 acc = make_float4(0.f, 0.f, 0.f, 0.f);
    int j = beg;
    for (; j + 3 < end; j += 4) {
        int   s0 = g_col[j],     s1 = g_col[j + 1], s2 = g_col[j + 2], s3 = g_col[j + 3];
        float w0 = g_val[j],     w1 = g_val[j + 1], w2 = g_val[j + 2], w3 = g_val[j + 3];
        if (act) {
            float4 v0 = *(const float4*)(g_h1 + s0 * H_DIM + off);
            float4 v1 = *(const float4*)(g_h1 + s1 * H_DIM + off);
            float4 v2 = *(const float4*)(g_h1 + s2 * H_DIM + off);
            float4 v3 = *(const float4*)(g_h1 + s3 * H_DIM + off);
            acc.x += w0 * v0.x + w1 * v1.x + w2 * v2.x + w3 * v3.x;
            acc.y += w0 * v0.y + w1 * v1.y + w2 * v2.y + w3 * v3.y;
            acc.z += w0 * v0.z + w1 * v1.z + w2 * v2.z + w3 * v3.z;
            acc.w += w0 * v0.w + w1 * v1.w + w2 * v2.w + w3 * v3.w;
        }
    }
    for (; j < end; j++) {
        int s = g_col[j]; float w = g_val[j];
        if (act) {
            float4 v = *(const float4*)(g_h1 + s * H_DIM + off);
            acc.x += w * v.x; acc.y += w * v.y; acc.z += w * v.z; acc.w += w * v.w;
        }
    }
    if (act) {
        float di = g_dinv[gw];
        float sl = di * di;
        float4 own = *(const float4*)(g_h1 + gw * H_DIM + off);
        float4 bb  = *(const float4*)(b1 + off);
        float4 r;
        r.x = acc.x + sl * own.x + bb.x;
        r.y = acc.y + sl * own.y + bb.y;
        r.z = acc.z + sl * own.z + bb.z;
        r.w = acc.w + sl * own.w + bb.w;
        r.x = (r.x > 0.f) ? r.x : LEAKY * r.x;
        r.y = (r.y > 0.f) ? r.y : LEAKY * r.y;
        r.z = (r.z > 0.f) ? r.z : LEAKY * r.z;
        r.w = (r.w > 0.f) ? r.w : LEAKY * r.w;
        *(float4*)(g_h1p + gw * H_DIM + off) = r;
    }
}

// ---------------------------------------------------------------- GEMM2: g_h2 = h1p @ W2  (N x 100 @ 100 x 16)
__global__ void k_gemm2(const float* __restrict__ W2) {
    __shared__ __align__(16) float sh[64][101];
    __shared__ __align__(16) float sw[H_DIM * C_DIM];

    int tid = threadIdx.x;
    int r0  = blockIdx.x * 64;

    for (int i = tid; i < H_DIM * C_DIM; i += 128) sw[i] = W2[i];
    for (int i = tid; i < 64 * H_DIM; i += 128) {
        int r = i / H_DIM, c = i - r * H_DIM;
        int gr = r0 + r;
        sh[r][c] = (gr < N_NODES) ? g_h1p[gr * H_DIM + c] : 0.f;
    }
    __syncthreads();

    int cg = tid & 3;
    int rg = tid >> 2;
    float a0x=0,a0y=0,a0z=0,a0w=0, a1x=0,a1y=0,a1z=0,a1w=0;

    #pragma unroll 4
    for (int k = 0; k < H_DIM; k++) {
        float x0 = sh[rg * 2 + 0][k];
        float x1 = sh[rg * 2 + 1][k];
        float4 w = *(const float4*)&sw[k * C_DIM + cg * 4];
        a0x += x0 * w.x;  a0y += x0 * w.y;  a0z += x0 * w.z;  a0w += x0 * w.w;
        a1x += x1 * w.x;  a1y += x1 * w.y;  a1z += x1 * w.z;  a1w += x1 * w.w;
    }

    int gr0 = r0 + rg * 2;
    if (gr0 < N_NODES)
        *(float4*)&g_h2[gr0 * C_DIM + cg * 4] = make_float4(a0x, a0y, a0z, a0w);
    if (gr0 + 1 < N_NODES)
        *(float4*)&g_h2[(gr0 + 1) * C_DIM + cg * 4] = make_float4(a1x, a1y, a1z, a1w);
}

// ---------------------------------------------------------------- prop2 fused: gather + self-loop + bias + log_softmax
__global__ void k_prop2f(const float* __restrict__ b2, float* __restrict__ out) {
    int gw   = (blockIdx.x * blockDim.x + threadIdx.x) >> 5;
    int lane = threadIdx.x & 31;
    if (gw >= N_NODES) return;
    int beg = g_rowptr[gw];
    int end = g_rowptr[gw + 1];
    int sub = lane >> 4;
    int f   = lane & 15;

    float acc = 0.f;
    for (int j = beg + sub; j < end; j += 2) {
        int s = g_col[j];
        float w = g_val[j];
        acc += w * g_h2[s * C_DIM + f];
    }
    acc += __shfl_xor_sync(0xFFFFFFFFu, acc, 16);

    float di = g_dinv[gw];
    float v = acc + di * di * g_h2[gw * C_DIM + f] + b2[f];

    float m = v;
    #pragma unroll
    for (int s = 8; s >= 1; s >>= 1) m = fmaxf(m, __shfl_xor_sync(0xFFFFFFFFu, m, s));
    float ex = expf(v - m);
    float ssum = ex;
    #pragma unroll
    for (int s = 8; s >= 1; s >>= 1) ssum += __shfl_xor_sync(0xFFFFFFFFu, ssum, s);
    if (lane < 16) out[gw * C_DIM + f] = v - m - logf(ssum);
}

// ---------------------------------------------------------------- launch
extern "C" void kernel_launch(void* const* d_in, const int* in_sizes, int n_in,
                              void* d_out, int out_size) {
    const float* x  = (const float*)d_in[0];
    const float* W1 = (const float*)d_in[1];
    const float* b1 = (const float*)d_in[2];
    const float* W2 = (const float*)d_in[3];
    const float* b2 = (const float*)d_in[4];
    const int*   ei = (const int*)d_in[5];
    const int* src = ei;
    const int* dst = ei + N_EDGES;
    float* out = (float*)d_out;

    // Fork GEMM1 onto a side stream; CSR build runs concurrently on the main stream.
    cudaStream_t s2;
    cudaStreamCreate(&s2);
    cudaEvent_t ev_fork, ev_join;
    cudaEventCreateWithFlags(&ev_fork, cudaEventDisableTiming);
    cudaEventCreateWithFlags(&ev_join, cudaEventDisableTiming);

    cudaEventRecord(ev_fork, 0);
    cudaStreamWaitEvent(s2, ev_fork, 0);
    k_gemm1<<< (N_NODES + 127) / 128, 256, 0, s2 >>> (x, W1);
    cudaEventRecord(ev_join, s2);

    k_zero  <<< (CNT_PAD + 255) / 256, 256 >>> ();
    k_count <<< (N_EDGES / 4 + 255) / 256, 256 >>> (dst);
    k_scan1 <<< SCAN_BLK, 256 >>> ();
    k_scan2 <<< 1, 64 >>> ();
    k_scan3 <<< SCAN_BLK, 256 >>> ();
    k_build <<< (N_EDGES / 4 + 255) / 256, 256 >>> (src, dst);

    cudaStreamWaitEvent(0, ev_join, 0);
    k_prop1f<<< (N_NODES * 32 + 255) / 256, 256 >>> (b1);
    k_gemm2 <<< (N_NODES + 63) / 64, 128 >>> (W2);
    k_prop2f<<< (N_NODES * 32 + 255) / 256, 256 >>> (b2, out);
}